// round 1
// baseline (speedup 1.0000x reference)
#include <cuda_runtime.h>

// ---------------- problem constants ----------------
#define TDIM   2048
#define BDIM   16384
#define NTS    18431            // TDIM + BDIM - 1
#define MQ     24               // seasonality period == HORIZON
#define XOUT_N (BDIM * TDIM)    // 33554432
#define DEN_N  (BDIM * 48)      // 786432

// ---------------- chunk-parallel scan config ----------------
#define W_UP   1440             // warm-up steps (multiple of 24)
#define CH_S   19               // chunk size (odd -> conflict-free smem stride)
#define K2_BT  128              // threads per scan block
#define K2_NB  8                // scan blocks
#define NCHUNK (K2_BT * K2_NB)  // 1024 chunk slots; 1024*19 = 19456 >= NTS
#define BSPAN  (K2_BT * CH_S)   // 2432 steps per block
#define SLICE  (W_UP + BSPAN)   // 3872 floats of ts per block

// ---------------- device scratch (no allocs allowed) ----------------
__device__ float g_ts[NTS];
__device__ float g_xn[NTS];
__device__ float g_l [NTS];
__device__ float g_s [NTS];
__device__ float g_lstart[NCHUNK];
__device__ float g_lend  [NCHUNK];

__device__ __forceinline__ float frcp(float x) {
    float r;
    asm("rcp.approx.ftz.f32 %0, %1;" : "=f"(r) : "f"(x));
    return r;
}

// K1: ts = concat(x[0, :, 0], x[1:, T-1, 0])
__global__ void k_build_ts(const float* __restrict__ x) {
    int i = blockIdx.x * blockDim.x + threadIdx.x;
    if (i < NTS)
        g_ts[i] = (i < TDIM) ? x[i] : x[(i - (TDIM - 1)) * TDIM + (TDIM - 1)];
}

// K2: chunk-parallel exact-mod-symmetry scan.
// Thread = one chunk of CH_S steps, warm-started W_UP steps earlier.
// Chunks whose warm-up clamps at t=0 start from the exact initial state.
__global__ __launch_bounds__(K2_BT) void k_scan(
    const float* __restrict__ alpha_p, const float* __restrict__ gamma_p,
    const float* __restrict__ inits,   const float* __restrict__ level_p)
{
    __shared__ float sm_ts[SLICE];
    __shared__ float sm_xn[BSPAN];
    __shared__ float sm_l [BSPAN];
    __shared__ float sm_s [BSPAN];

    const int blk_t0     = blockIdx.x * BSPAN;
    const int slice_base = blk_t0 - W_UP;

    // cooperative coalesced load of the ts slice this block needs
    for (int idx = threadIdx.x; idx < SLICE; idx += K2_BT) {
        int u = slice_base + idx;
        sm_ts[idx] = (u >= 0 && u < NTS) ? g_ts[u] : 1.0f;
    }
    __syncthreads();

    const float a  = *alpha_p;
    const float g  = *gamma_p;
    const float ka = 1.0f - a;
    const float kg = 1.0f - g;

    const int chunk = blockIdx.x * K2_BT + threadIdx.x;
    const int t0    = chunk * CH_S;
    const int tend  = (t0 + CH_S < NTS) ? (t0 + CH_S) : NTS;
    const int u0    = t0 - W_UP;

    float l = *level_p;
    float q[MQ];
    // Align queue slots so that at u=0 (exact-start case) slot j0 holds inits[0].
    // Slot used at step u is (u - u0) mod 24; j0 = (-u0) mod 24.
    int j0 = ((-u0) % MQ + MQ) % MQ;
#pragma unroll
    for (int j = 0; j < MQ; j++)
        q[j] = inits[(j - j0 + 2 * MQ) % MQ];   // static write idx -> stays in regs

    const int NMACRO = (W_UP + CH_S + MQ - 1) / MQ;   // 61
    for (int kk = 0; kk < NMACRO; kk++) {
#pragma unroll
        for (int j = 0; j < MQ; j++) {
            int u = u0 + kk * MQ + j;
            if (u >= 0 && u < tend) {
                if (u == t0) g_lstart[chunk] = l;        // level entering the chunk
                float y    = sm_ts[u - slice_base];
                float s    = q[j];
                float r    = y * frcp(s);                // y / s_t
                l          = fmaf(ka, l, a * r);         // new level
                float invl = frcp(l);
                float sn   = fmaf(kg, s, (g * y) * invl); // new seasonality
                q[j]       = sn;                          // consumed again in 24 steps
                if (u >= t0) {
                    int o = u - blk_t0;
                    sm_xn[o] = r * invl;                 // y / (s_t * l_t)
                    sm_l [o] = l;
                    sm_s [o] = sn;
                }
            }
        }
    }
    if (t0 < NTS) g_lend[chunk] = l;                     // level entering tend

    __syncthreads();
    int span = NTS - blk_t0; if (span > BSPAN) span = BSPAN;
    for (int idx = threadIdx.x; idx < span; idx += K2_BT) {
        g_xn[blk_t0 + idx] = sm_xn[idx];
        g_l [blk_t0 + idx] = sm_l [idx];
        g_s [blk_t0 + idx] = sm_s [idx];
    }
}

// K3: symmetry-mode correction. ratio_k = lstart_k / lend_{k-1} = c_k / c_{k-1};
// prefix product gives c_k; true l = l/c, true s = s*c. xn is invariant.
__global__ __launch_bounds__(NCHUNK) void k_correct() {
    __shared__ float c[NCHUNK];
    int k = threadIdx.x;
    float ratio = 1.0f;
    if (k > 0 && k * CH_S < NTS) ratio = g_lstart[k] / g_lend[k - 1];
    c[k] = ratio;
    __syncthreads();
    for (int off = 1; off < NCHUNK; off <<= 1) {
        float v = (k >= off) ? c[k - off] : 1.0f;
        __syncthreads();
        c[k] *= v;
        __syncthreads();
    }
    for (int t = k; t < NTS; t += NCHUNK) {
        float cc = c[t / CH_S];
        g_l[t] = g_l[t] / cc;
        g_s[t] = g_s[t] * cc;
    }
}

// K4a: x_out[b, t] = xn[b + t]   (store-bandwidth bound; vectorized stores,
// scalar L1-resident loads since xn is only 72KB)
__global__ void k_xout(float* __restrict__ out) {
    int i4 = blockIdx.x * blockDim.x + threadIdx.x;   // 8,388,608 float4s
    int i  = i4 << 2;
    int b  = i >> 11;
    int t  = i & (TDIM - 1);
    int base = b + t;
    float4 v;
    v.x = g_xn[base];
    v.y = g_xn[base + 1];
    v.z = g_xn[base + 2];
    v.w = g_xn[base + 3];
    reinterpret_cast<float4*>(out)[i4] = v;
}

// K4b: denorm[b, h, 0] = l[T-1+b]; denorm[b, h, 1] = snew[T-24 + b + h]
__global__ void k_denorm(float* __restrict__ out) {
    int i = blockIdx.x * blockDim.x + threadIdx.x;
    if (i < DEN_N) {
        int b = i / 48;
        int r = i - b * 48;
        int h = r >> 1;
        out[XOUT_N + i] = (r & 1) ? g_s[(TDIM - MQ) + b + h]
                                  : g_l[(TDIM - 1) + b];
    }
}

extern "C" void kernel_launch(void* const* d_in, const int* in_sizes, int n_in,
                              void* d_out, int out_size) {
    const float* x     = (const float*)d_in[0];
    const float* alpha = (const float*)d_in[1];
    const float* gamma = (const float*)d_in[2];
    const float* inits = (const float*)d_in[3];
    const float* level = (const float*)d_in[4];
    float* out = (float*)d_out;

    k_build_ts<<<(NTS + 255) / 256, 256>>>(x);
    k_scan<<<K2_NB, K2_BT>>>(alpha, gamma, inits, level);
    k_correct<<<1, NCHUNK>>>();
    k_xout<<<XOUT_N / 4 / 256, 256>>>(out);
    if (out_size >= XOUT_N + DEN_N)
        k_denorm<<<(DEN_N + 255) / 256, 256>>>(out);
}

// round 3
// speedup vs baseline: 1.0613x; 1.0613x over previous
#include <cuda_runtime.h>

// ---------------- problem constants ----------------
#define TDIM   2048
#define BDIM   16384
#define NTS    18431            // TDIM + BDIM - 1
#define MQ     24               // seasonality period == HORIZON
#define XOUT_N (BDIM * TDIM)    // 33554432
#define DEN_N  (BDIM * 48)      // 786432

// ---------------- chunk-parallel scan config (R1 numerics, bitwise) --------
#define W_UP   1440             // warm-up steps (60 cycles) -- EXACTLY R1
#define WMACRO (W_UP / MQ)      // 60
#define CH_S   19               // chunk size (odd -> conflict-free smem)
#define K2_BT  32               // 1 warp per block -> 1 warp/SMSP, many SMs
#define K2_NB  31               // 31 blocks cover chunks 0..991 (970 needed)
#define NCHUNK 1024             // logical chunk-index space (as in R1)
#define BSPAN  (K2_BT * CH_S)   // 608 steps per block
#define SLICE  (W_UP + BSPAN)   // 2048 floats of ts per block

// ---------------- device scratch (no allocs allowed) ----------------
__device__ __align__(16) float g_xn[18448];   // padded so float4 reads stay in-bounds
__device__ float g_l [NTS];
__device__ float g_s [NTS];
__device__ float g_lstart[NCHUNK];
__device__ float g_lend  [NCHUNK];

__device__ __forceinline__ float frcp(float x) {
    float r;
    asm("rcp.approx.ftz.f32 %0, %1;" : "=f"(r) : "f"(x));
    return r;
}

// ============ K1: chunk-parallel exact-mod-symmetry scan ============
// Per-step FP sequence is EXACTLY R1's: r = y*rcp(s); l = fma(ka,l,a*r);
// sn = fma(kg,s,(g*y)*rcp(l)). Warm-started chunks converge to truth modulo
// the exact symmetry (l,q)->(c*l,q/c); c fixed later by prefix product.
__global__ __launch_bounds__(K2_BT) void k_scan(
    const float* __restrict__ x,
    const float* __restrict__ alpha_p, const float* __restrict__ gamma_p,
    const float* __restrict__ inits,   const float* __restrict__ level_p)
{
    __shared__ float sm_ts[SLICE];
    __shared__ float sm_xn[BSPAN];
    __shared__ float sm_l [BSPAN];
    __shared__ float sm_s [BSPAN];

    const int tid        = threadIdx.x;
    const int blk_t0     = blockIdx.x * BSPAN;
    const int slice_base = blk_t0 - W_UP;

    // stage ts slice: ts[u] = (u < T) ? x[0,u,0] : x[u-T+1, T-1, 0]
    #pragma unroll 4
    for (int idx = tid; idx < SLICE; idx += K2_BT) {
        int u = slice_base + idx;
        float v = 1.0f;
        if (u >= 0 && u < NTS)
            v = (u < TDIM) ? x[u] : x[(u - (TDIM - 1)) * TDIM + (TDIM - 1)];
        sm_ts[idx] = v;
    }
    __syncthreads();

    const float a  = *alpha_p;
    const float g  = *gamma_p;
    const float ka = 1.0f - a;
    const float kg = 1.0f - g;

    const int chunk = blockIdx.x * K2_BT + tid;
    const int t0    = chunk * CH_S;
    const int u0    = t0 - W_UP;

    float l = *level_p;
    float q[MQ];
    // slot used at step u is (u - u0) mod 24; since W_UP % 24 == 0 this is
    // (u - t0) mod 24, so q[j] = inits[(j + t0) % 24] puts inits[0] at u = 0.
    {
        int ph = t0 % MQ;
#pragma unroll
        for (int j = 0; j < MQ; j++) {
            int idx = j + ph; if (idx >= MQ) idx -= MQ;
            q[j] = inits[idx];
        }
    }

    int off = tid * CH_S;   // sm_ts index of this thread's u0

    if (u0 < 0) {
        // clamped warm-up (chunks with t0 < W_UP): skip steps before t=0,
        // identical to R1's guarded loop
        int u = u0;
        for (int kk = 0; kk < WMACRO; kk++) {
#pragma unroll
            for (int j = 0; j < MQ; j++) {
                float y = sm_ts[off + j];
                if (u >= 0) {
                    float s = q[j];
                    float r = y * frcp(s);
                    l = fmaf(ka, l, a * r);
                    q[j] = fmaf(kg, s, (g * y) * frcp(l));
                }
                u++;
            }
            off += MQ;
        }
    } else {
        // clean warm loop: rcp(q[j]) inputs are 24 steps ahead of use, so the
        // compiler can hoist them; cross-step chain is the single level FMA.
        for (int kk = 0; kk < WMACRO; kk++) {
#pragma unroll
            for (int j = 0; j < MQ; j++) {
                float y = sm_ts[off + j];
                float s = q[j];
                float r = y * frcp(s);
                l = fmaf(ka, l, a * r);
                q[j] = fmaf(kg, s, (g * y) * frcp(l));
            }
            off += MQ;
        }
    }

    g_lstart[chunk] = l;                  // level entering t0 (pre-update)

    // output phase: 19 steps; slots wrap from 0 since W_UP % 24 == 0
    const int oo = tid * CH_S;
#pragma unroll
    for (int c = 0; c < CH_S; c++) {
        float y    = sm_ts[off + c];
        float s    = q[c];
        float r    = y * frcp(s);
        l          = fmaf(ka, l, a * r);
        float invl = frcp(l);
        float sn   = fmaf(kg, s, (g * y) * invl);
        sm_xn[oo + c] = r * invl;
        sm_l [oo + c] = l;
        sm_s [oo + c] = sn;
    }
    g_lend[chunk] = l;                    // level entering t0 + 19

    __syncthreads();
    int span = NTS - blk_t0; if (span > BSPAN) span = BSPAN;
    for (int idx = tid; idx < span; idx += K2_BT) {
        g_xn[blk_t0 + idx] = sm_xn[idx];
        g_l [blk_t0 + idx] = sm_l [idx];
        g_s [blk_t0 + idx] = sm_s [idx];
    }
}

// ============ K2: prefix product + in-place correction (R1 verbatim) ======
// ratio_k = lstart_k / lend_{k-1} = c_k / c_{k-1}; c_0 = 1 (exact start).
// xn is symmetry-invariant; l,s corrected in place.
__global__ __launch_bounds__(NCHUNK) void k_correct() {
    __shared__ float c[NCHUNK];
    int k = threadIdx.x;
    float ratio = 1.0f;
    if (k > 0 && k * CH_S < NTS) ratio = g_lstart[k] / g_lend[k - 1];
    c[k] = ratio;
    __syncthreads();
    for (int o = 1; o < NCHUNK; o <<= 1) {
        float v = (k >= o) ? c[k - o] : 1.0f;
        __syncthreads();
        c[k] *= v;
        __syncthreads();
    }
    for (int t = k; t < NTS; t += NCHUNK) {
        float cc = c[t / CH_S];
        g_l[t] = g_l[t] / cc;
        g_s[t] = g_s[t] * cc;
    }
}

// ============ K3: x_out[b,t] = xn[b+t] ============
// 2 aligned LDG.128 + warp-uniform shift mux per float4 stored (validated R2).
__global__ void k_xout(float* __restrict__ out) {
    int i4   = blockIdx.x * blockDim.x + threadIdx.x;
    int i    = i4 << 2;
    int b    = i >> 11;
    int t    = i & (TDIM - 1);
    int base = b + t;
    int qq   = base >> 2;
    int sh   = base & 3;
    const float4* xn4 = reinterpret_cast<const float4*>(g_xn);
    float4 f0 = xn4[qq];
    float4 v;
    if (sh == 0) {
        v = f0;
    } else {
        float4 f1 = xn4[qq + 1];
        if (sh == 1)      v = make_float4(f0.y, f0.z, f0.w, f1.x);
        else if (sh == 2) v = make_float4(f0.z, f0.w, f1.x, f1.y);
        else              v = make_float4(f0.w, f1.x, f1.y, f1.z);
    }
    reinterpret_cast<float4*>(out)[i4] = v;
}

// ============ K4: denorm (R1 verbatim) ============
// denorm[b,h,0] = l[T-1+b]; denorm[b,h,1] = s_new[T-24 + b + h]
__global__ void k_denorm(float* __restrict__ out) {
    int i = blockIdx.x * blockDim.x + threadIdx.x;
    if (i < DEN_N) {
        int b = i / 48;
        int r = i - b * 48;
        int h = r >> 1;
        out[XOUT_N + i] = (r & 1) ? g_s[(TDIM - MQ) + b + h]
                                  : g_l[(TDIM - 1) + b];
    }
}

extern "C" void kernel_launch(void* const* d_in, const int* in_sizes, int n_in,
                              void* d_out, int out_size) {
    const float* x     = (const float*)d_in[0];
    const float* alpha = (const float*)d_in[1];
    const float* gamma = (const float*)d_in[2];
    const float* inits = (const float*)d_in[3];
    const float* level = (const float*)d_in[4];
    float* out = (float*)d_out;

    k_scan<<<K2_NB, K2_BT>>>(x, alpha, gamma, inits, level);
    k_correct<<<1, NCHUNK>>>();
    k_xout<<<XOUT_N / 4 / 256, 256>>>(out);
    if (out_size >= XOUT_N + DEN_N)
        k_denorm<<<(DEN_N + 255) / 256, 256>>>(out);
}

// round 4
// speedup vs baseline: 1.0737x; 1.0116x over previous
#include <cuda_runtime.h>

// ---------------- problem constants ----------------
#define TDIM   2048
#define BDIM   16384
#define NTS    18431            // TDIM + BDIM - 1
#define MQ     24               // seasonality period == HORIZON
#define XOUT_N (BDIM * TDIM)    // 33554432
#define DEN_N  (BDIM * 48)      // 786432

// ---------------- chunk-parallel scan config (R1 numerics, bitwise) --------
#define W_UP   1440             // warm-up steps (60 cycles) -- EXACTLY R1
#define WMACRO (W_UP / MQ)      // 60
#define CH_S   19               // chunk size (odd -> conflict-free smem)
#define K2_BT  32               // 1 warp per block
#define K2_NB  31               // 992 chunks cover the 970 needed
#define NCHUNK 1024             // logical chunk-index space (as in R1)
#define BSPAN  (K2_BT * CH_S)   // 608 steps per block
#define SLICE  (W_UP + BSPAN)   // 2048 floats of ts per block

#define XB     (XOUT_N / 4 / 256)        // 32768 xout blocks
#define DB     ((DEN_N + 255) / 256)     // 3072 denorm blocks

// ---------------- device scratch (no allocs allowed) ----------------
__device__ __align__(16) float g_xn[18448];   // padded so float4 reads stay in-bounds
__device__ float g_l [NTS];
__device__ float g_s [NTS];
__device__ float g_lstart[NCHUNK];
__device__ float g_lend  [NCHUNK];

__device__ __forceinline__ float frcp(float x) {
    float r;
    asm("rcp.approx.ftz.f32 %0, %1;" : "=f"(r) : "f"(x));
    return r;
}

// ============ K1: chunk-parallel exact-mod-symmetry scan ============
// Software-pipelined but BITWISE identical to R1/R3 numerics:
//   iq[j] = rcp(q[j]) is computed at write time (24 steps before use), so
//   r = y*iq[j] == y*rcp(s) exactly. Per-step loop-carried chain is just the
//   level FFMA; both MUFU results have 24 steps of slack.
__global__ __launch_bounds__(K2_BT) void k_scan(
    const float* __restrict__ x,
    const float* __restrict__ alpha_p, const float* __restrict__ gamma_p,
    const float* __restrict__ inits,   const float* __restrict__ level_p)
{
    __shared__ float sm_ts[SLICE];
    __shared__ float sm_xn[BSPAN];
    __shared__ float sm_l [BSPAN];
    __shared__ float sm_s [BSPAN];

    const int tid        = threadIdx.x;
    const int blk_t0     = blockIdx.x * BSPAN;
    const int slice_base = blk_t0 - W_UP;

    // stage ts slice: ts[u] = (u < T) ? x[0,u,0] : x[u-T+1, T-1, 0]
    #pragma unroll 4
    for (int idx = tid; idx < SLICE; idx += K2_BT) {
        int u = slice_base + idx;
        float v = 1.0f;
        if (u >= 0 && u < NTS)
            v = (u < TDIM) ? x[u] : x[(u - (TDIM - 1)) * TDIM + (TDIM - 1)];
        sm_ts[idx] = v;
    }
    __syncthreads();

    const float a  = *alpha_p;
    const float g  = *gamma_p;
    const float ka = 1.0f - a;
    const float kg = 1.0f - g;

    const int chunk = blockIdx.x * K2_BT + tid;
    const int t0    = chunk * CH_S;
    const int u0    = t0 - W_UP;

    float l = *level_p;
    float q[MQ];
    float iq[MQ];
    // slot used at step u is (u - u0) mod 24; since W_UP % 24 == 0 this is
    // (u - t0) mod 24, so q[j] = inits[(j + t0) % 24] puts inits[0] at u = 0.
    {
        int ph = t0 % MQ;
#pragma unroll
        for (int j = 0; j < MQ; j++) {
            int idx = j + ph; if (idx >= MQ) idx -= MQ;
            q[j]  = inits[idx];
        }
#pragma unroll
        for (int j = 0; j < MQ; j++) iq[j] = frcp(q[j]);
    }

    int off = tid * CH_S;   // sm_ts index of this thread's u0

    if (u0 < 0) {
        // clamped warm-up (chunks with t0 < W_UP): skip steps before t=0.
        // Same FP sequence as the clean loop for u >= 0.
        int u = u0;
        for (int kk = 0; kk < WMACRO; kk++) {
#pragma unroll
            for (int j = 0; j < MQ; j++) {
                float y = sm_ts[off + j];
                if (u >= 0) {
                    float r  = y * iq[j];
                    l        = fmaf(ka, l, a * r);
                    float il = frcp(l);
                    float sn = fmaf(kg, q[j], (g * y) * il);
                    q[j]  = sn;
                    iq[j] = frcp(sn);
                }
                u++;
            }
            off += MQ;
        }
    } else {
        // clean warm loop: 1 LDS + 2 MUFU + 3 FMUL + 2 FFMA per step;
        // only the level FFMA is loop-carried.
        for (int kk = 0; kk < WMACRO; kk++) {
#pragma unroll
            for (int j = 0; j < MQ; j++) {
                float y  = sm_ts[off + j];
                float r  = y * iq[j];
                l        = fmaf(ka, l, a * r);
                float il = frcp(l);
                float sn = fmaf(kg, q[j], (g * y) * il);
                q[j]  = sn;
                iq[j] = frcp(sn);
            }
            off += MQ;
        }
    }

    g_lstart[chunk] = l;                  // level entering t0 (pre-update)

    // output phase: 19 steps; slots wrap from 0 since W_UP % 24 == 0
    const int oo = tid * CH_S;
#pragma unroll
    for (int c = 0; c < CH_S; c++) {
        float y    = sm_ts[off + c];
        float r    = y * iq[c];
        l          = fmaf(ka, l, a * r);
        float il   = frcp(l);
        float sn   = fmaf(kg, q[c], (g * y) * il);
        sm_xn[oo + c] = r * il;
        sm_l [oo + c] = l;
        sm_s [oo + c] = sn;
    }
    g_lend[chunk] = l;                    // level entering t0 + 19

    __syncthreads();
    int span = NTS - blk_t0; if (span > BSPAN) span = BSPAN;
    for (int idx = tid; idx < span; idx += K2_BT) {
        g_xn[blk_t0 + idx] = sm_xn[idx];
        g_l [blk_t0 + idx] = sm_l [idx];
        g_s [blk_t0 + idx] = sm_s [idx];
    }
}

// ============ K2: prefix product + in-place correction (R1 verbatim) ======
__global__ __launch_bounds__(NCHUNK) void k_correct() {
    __shared__ float c[NCHUNK];
    int k = threadIdx.x;
    float ratio = 1.0f;
    if (k > 0 && k * CH_S < NTS) ratio = g_lstart[k] / g_lend[k - 1];
    c[k] = ratio;
    __syncthreads();
    for (int o = 1; o < NCHUNK; o <<= 1) {
        float v = (k >= o) ? c[k - o] : 1.0f;
        __syncthreads();
        c[k] *= v;
        __syncthreads();
    }
    for (int t = k; t < NTS; t += NCHUNK) {
        float cc = c[t / CH_S];
        g_l[t] = g_l[t] / cc;
        g_s[t] = g_s[t] * cc;
    }
}

// ============ K3: fused x_out + denorm ============
// Blocks [0, XB): x_out[b,t] = xn[b+t] via 2 aligned LDG.128 + warp-uniform mux.
// Blocks [XB, XB+DB): denorm (R1 semantics, reads corrected g_l/g_s).
__global__ void k_out(float* __restrict__ out) {
    int bx = blockIdx.x;
    if (bx < XB) {
        int i4   = bx * blockDim.x + threadIdx.x;
        int i    = i4 << 2;
        int b    = i >> 11;
        int t    = i & (TDIM - 1);
        int base = b + t;
        int qq   = base >> 2;
        int sh   = base & 3;
        const float4* xn4 = reinterpret_cast<const float4*>(g_xn);
        float4 f0 = xn4[qq];
        float4 v;
        if (sh == 0) {
            v = f0;
        } else {
            float4 f1 = xn4[qq + 1];
            if (sh == 1)      v = make_float4(f0.y, f0.z, f0.w, f1.x);
            else if (sh == 2) v = make_float4(f0.z, f0.w, f1.x, f1.y);
            else              v = make_float4(f0.w, f1.x, f1.y, f1.z);
        }
        reinterpret_cast<float4*>(out)[i4] = v;
    } else {
        int i = (bx - XB) * blockDim.x + threadIdx.x;
        if (i < DEN_N) {
            int b = i / 48;
            int r = i - b * 48;
            int h = r >> 1;
            out[XOUT_N + i] = (r & 1) ? g_s[(TDIM - MQ) + b + h]
                                      : g_l[(TDIM - 1) + b];
        }
    }
}

extern "C" void kernel_launch(void* const* d_in, const int* in_sizes, int n_in,
                              void* d_out, int out_size) {
    const float* x     = (const float*)d_in[0];
    const float* alpha = (const float*)d_in[1];
    const float* gamma = (const float*)d_in[2];
    const float* inits = (const float*)d_in[3];
    const float* level = (const float*)d_in[4];
    float* out = (float*)d_out;

    k_scan<<<K2_NB, K2_BT>>>(x, alpha, gamma, inits, level);
    k_correct<<<1, NCHUNK>>>();
    int nb = (out_size >= XOUT_N + DEN_N) ? (XB + DB) : XB;
    k_out<<<nb, 256>>>(out);
}

// round 5
// speedup vs baseline: 1.6400x; 1.5275x over previous
#include <cuda_runtime.h>

// ---------------- problem constants ----------------
#define TDIM   2048
#define BDIM   16384
#define NTS    18431            // TDIM + BDIM - 1
#define MQ     24               // seasonality period == HORIZON
#define XOUT_N (BDIM * TDIM)    // 33554432
#define DEN_N  (BDIM * 48)      // 786432

// ---------------- chunk-parallel scan config (R1 numerics, bitwise) --------
#define W_UP   1440             // warm-up steps (60 cycles) -- EXACTLY R1
#define WMACRO (W_UP / MQ)      // 60
#define CH_S   19               // chunk size (odd -> conflict-free smem)
#define K2_BT  32               // 1 warp per block
#define K2_NB  31               // 992 chunks cover the 970 needed
#define NCHUNK 1024             // logical chunk-index space (as in R1)
#define BSPAN  (K2_BT * CH_S)   // 608 steps per block
#define SLICE  (W_UP + BSPAN)   // 2048 floats of ts per block

#define XB     (XOUT_N / 4 / 256)        // 32768 xout blocks
#define DB     ((DEN_N + 255) / 256)     // 3072 denorm blocks

// ---------------- device scratch (no allocs allowed) ----------------
__device__ __align__(16) float g_xn[18448];   // padded so float4 reads stay in-bounds
__device__ float g_l [NTS];
__device__ float g_s [NTS];
__device__ float g_lstart[NCHUNK];
__device__ float g_lend  [NCHUNK];

__device__ __forceinline__ float frcp(float x) {
    float r;
    asm("rcp.approx.ftz.f32 %0, %1;" : "=f"(r) : "f"(x));
    return r;
}

// ============ K1: chunk-parallel exact-mod-symmetry scan ============
// BITWISE identical value graph to R1/R3/R4; only the schedule changed.
// Each 24-step macro is phase-decomposed so the only serial chain ptxas can
// see is the 24-FFMA level chain; the 48 MUFU.RCPs per macro are independent.
__global__ __launch_bounds__(K2_BT) void k_scan(
    const float* __restrict__ x,
    const float* __restrict__ alpha_p, const float* __restrict__ gamma_p,
    const float* __restrict__ inits,   const float* __restrict__ level_p)
{
    __shared__ float sm_ts[SLICE];
    __shared__ float sm_xn[BSPAN];
    __shared__ float sm_l [BSPAN];
    __shared__ float sm_s [BSPAN];

    const int tid        = threadIdx.x;
    const int blk_t0     = blockIdx.x * BSPAN;
    const int slice_base = blk_t0 - W_UP;

    // stage ts slice: ts[u] = (u < T) ? x[0,u,0] : x[u-T+1, T-1, 0]
    #pragma unroll 4
    for (int idx = tid; idx < SLICE; idx += K2_BT) {
        int u = slice_base + idx;
        float v = 1.0f;
        if (u >= 0 && u < NTS)
            v = (u < TDIM) ? x[u] : x[(u - (TDIM - 1)) * TDIM + (TDIM - 1)];
        sm_ts[idx] = v;
    }
    __syncthreads();

    const float a  = *alpha_p;
    const float g  = *gamma_p;
    const float ka = 1.0f - a;
    const float kg = 1.0f - g;

    const int chunk = blockIdx.x * K2_BT + tid;
    const int t0    = chunk * CH_S;
    const int u0    = t0 - W_UP;

    float l = *level_p;
    float q[MQ];
    float iq[MQ];
    // slot used at step u is (u - u0) mod 24 == (u - t0) mod 24 (W_UP%24==0);
    // q[j] = inits[(j + t0) % 24] puts inits[0] at u = 0.
    {
        int ph = t0 % MQ;
#pragma unroll
        for (int j = 0; j < MQ; j++) {
            int idx = j + ph; if (idx >= MQ) idx -= MQ;
            q[j] = inits[idx];
        }
#pragma unroll
        for (int j = 0; j < MQ; j++) iq[j] = frcp(q[j]);
    }

    const int base = tid * CH_S;   // sm_ts index of this thread's u0

    // ---- clamped prefix (threads with t0 < W_UP; blocks 0..2 only) ----
    // macros fully below t=0 are skipped; at most one macro is step-guarded.
    int kk = 0;
    if (u0 < 0) {
        int m   = (-u0) / MQ;      // fully-skipped macros
        int rem = (-u0) % MQ;      // first 'rem' steps of macro m are skipped
        kk = m;
        if (rem > 0) {
            int off = base + kk * MQ;
#pragma unroll
            for (int j = 0; j < MQ; j++) {
                if (j >= rem) {
                    float y  = sm_ts[off + j];
                    float r  = y * iq[j];
                    l        = fmaf(ka, l, a * r);
                    float il = frcp(l);
                    float sn = fmaf(kg, q[j], (g * y) * il);
                    q[j]  = sn;
                    iq[j] = frcp(sn);
                }
            }
            kk++;
        }
    }

    // ---- clean warm loop: phase-decomposed 24-step macros ----
    for (; kk < WMACRO; kk++) {
        const int off = base + kk * MQ;
        float y[MQ];
        float r[MQ];
        // phase 1: batched loads (one LDS latency per macro, not per step)
#pragma unroll
        for (int j = 0; j < MQ; j++) y[j] = sm_ts[off + j];
        // phase 2: independent ratios (iq from previous macro)
#pragma unroll
        for (int j = 0; j < MQ; j++) r[j] = y[j] * iq[j];
        // phase 3: the true serial chain -- 24 dependent FFMAs (4 cyc each);
        // r[j] reused to record the level trajectory
#pragma unroll
        for (int j = 0; j < MQ; j++) { l = fmaf(ka, l, a * r[j]); r[j] = l; }
        // phase 4: 24 independent rebuilds (2 pipelined MUFUs each)
#pragma unroll
        for (int j = 0; j < MQ; j++) {
            float il = frcp(r[j]);
            float sn = fmaf(kg, q[j], (g * y[j]) * il);
            q[j]  = sn;
            iq[j] = frcp(sn);
        }
    }

    g_lstart[chunk] = l;                  // level entering t0 (pre-update)

    // ---- output phase: 19 steps; slots wrap from 0 (W_UP % 24 == 0) ----
    {
        const int off = base + WMACRO * MQ;
        const int oo  = tid * CH_S;
        float y[CH_S];
        float r[CH_S];
#pragma unroll
        for (int c = 0; c < CH_S; c++) y[c] = sm_ts[off + c];
#pragma unroll
        for (int c = 0; c < CH_S; c++) r[c] = y[c] * iq[c];
#pragma unroll
        for (int c = 0; c < CH_S; c++) { l = fmaf(ka, l, a * r[c]); sm_l[oo + c] = l; r[c] = l; }
#pragma unroll
        for (int c = 0; c < CH_S; c++) {
            float il = frcp(r[c]);
            float sn = fmaf(kg, q[c], (g * y[c]) * il);
            sm_xn[oo + c] = (y[c] * iq[c]) * il;   // == r_c * il bitwise
            sm_s [oo + c] = sn;
        }
    }
    g_lend[chunk] = l;                    // level entering t0 + 19

    __syncthreads();
    int span = NTS - blk_t0; if (span > BSPAN) span = BSPAN;
    for (int idx = tid; idx < span; idx += K2_BT) {
        g_xn[blk_t0 + idx] = sm_xn[idx];
        g_l [blk_t0 + idx] = sm_l [idx];
        g_s [blk_t0 + idx] = sm_s [idx];
    }
}

// ============ K2: prefix product + in-place correction (R1 verbatim) ======
__global__ __launch_bounds__(NCHUNK) void k_correct() {
    __shared__ float c[NCHUNK];
    int k = threadIdx.x;
    float ratio = 1.0f;
    if (k > 0 && k * CH_S < NTS) ratio = g_lstart[k] / g_lend[k - 1];
    c[k] = ratio;
    __syncthreads();
    for (int o = 1; o < NCHUNK; o <<= 1) {
        float v = (k >= o) ? c[k - o] : 1.0f;
        __syncthreads();
        c[k] *= v;
        __syncthreads();
    }
    for (int t = k; t < NTS; t += NCHUNK) {
        float cc = c[t / CH_S];
        g_l[t] = g_l[t] / cc;
        g_s[t] = g_s[t] * cc;
    }
}

// ============ K3: fused x_out + denorm ============
__global__ void k_out(float* __restrict__ out) {
    int bx = blockIdx.x;
    if (bx < XB) {
        int i4   = bx * blockDim.x + threadIdx.x;
        int i    = i4 << 2;
        int b    = i >> 11;
        int t    = i & (TDIM - 1);
        int base = b + t;
        int qq   = base >> 2;
        int sh   = base & 3;
        const float4* xn4 = reinterpret_cast<const float4*>(g_xn);
        float4 f0 = xn4[qq];
        float4 v;
        if (sh == 0) {
            v = f0;
        } else {
            float4 f1 = xn4[qq + 1];
            if (sh == 1)      v = make_float4(f0.y, f0.z, f0.w, f1.x);
            else if (sh == 2) v = make_float4(f0.z, f0.w, f1.x, f1.y);
            else              v = make_float4(f0.w, f1.x, f1.y, f1.z);
        }
        reinterpret_cast<float4*>(out)[i4] = v;
    } else {
        int i = (bx - XB) * blockDim.x + threadIdx.x;
        if (i < DEN_N) {
            int b = i / 48;
            int r = i - b * 48;
            int h = r >> 1;
            out[XOUT_N + i] = (r & 1) ? g_s[(TDIM - MQ) + b + h]
                                      : g_l[(TDIM - 1) + b];
        }
    }
}

extern "C" void kernel_launch(void* const* d_in, const int* in_sizes, int n_in,
                              void* d_out, int out_size) {
    const float* x     = (const float*)d_in[0];
    const float* alpha = (const float*)d_in[1];
    const float* gamma = (const float*)d_in[2];
    const float* inits = (const float*)d_in[3];
    const float* level = (const float*)d_in[4];
    float* out = (float*)d_out;

    k_scan<<<K2_NB, K2_BT>>>(x, alpha, gamma, inits, level);
    k_correct<<<1, NCHUNK>>>();
    int nb = (out_size >= XOUT_N + DEN_N) ? (XB + DB) : XB;
    k_out<<<nb, 256>>>(out);
}

// round 6
// speedup vs baseline: 1.6673x; 1.0166x over previous
#include <cuda_runtime.h>

// ---------------- problem constants ----------------
#define TDIM   2048
#define BDIM   16384
#define NTS    18431            // TDIM + BDIM - 1
#define MQ     24               // seasonality period == HORIZON
#define XOUT_N (BDIM * TDIM)    // 33554432
#define DEN_N  (BDIM * 48)      // 786432

// ---------------- chunk-parallel scan config (R1 numerics, bitwise) --------
#define W_UP   1440             // warm-up steps (60 cycles) -- EXACTLY R1
#define WMACRO (W_UP / MQ)      // 60
#define CH_S   19               // chunk size (odd -> conflict-free smem)
#define K2_BT  32               // 1 warp per block
#define K2_NB  31               // 992 chunks cover the 970 needed
#define NCHUNK 1024             // logical chunk-index space (as in R1)
#define BSPAN  (K2_BT * CH_S)   // 608 steps per block
#define SLICE  (W_UP + BSPAN)   // 2048 floats of ts per block

#define XB     (XOUT_N / 4 / 256)        // 32768 xout blocks
#define DB     ((DEN_N + 255) / 256)     // 3072 denorm blocks

// ---------------- device scratch (no allocs allowed) ----------------
__device__ __align__(16) float g_xn[18448];   // padded so float4 reads stay in-bounds
__device__ float g_l [NTS];
__device__ float g_s [NTS];
__device__ float g_lstart[NCHUNK];
__device__ float g_lend  [NCHUNK];

__device__ __forceinline__ float frcp(float x) {
    float r;
    asm("rcp.approx.ftz.f32 %0, %1;" : "=f"(r) : "f"(x));
    return r;
}

// ============ K1: chunk-parallel exact-mod-symmetry scan ============
// BITWISE identical value graph to R1/R3/R4/R5; only the schedule changed.
// Per 24-step macro: batched loads; independent ratio FMULs; the serial
// 24-FFMA level chain; then THREE internally-independent sub-phases
// (24 RCP | 24 FMUL+FFMA | 24 RCP) so the MUFUs pipeline at rt=8.
__global__ __launch_bounds__(K2_BT) void k_scan(
    const float* __restrict__ x,
    const float* __restrict__ alpha_p, const float* __restrict__ gamma_p,
    const float* __restrict__ inits,   const float* __restrict__ level_p)
{
    __shared__ float sm_ts[SLICE];
    __shared__ float sm_xn[BSPAN];
    __shared__ float sm_l [BSPAN];
    __shared__ float sm_s [BSPAN];

    const int tid        = threadIdx.x;
    const int blk_t0     = blockIdx.x * BSPAN;
    const int slice_base = blk_t0 - W_UP;

    // stage ts slice: ts[u] = (u < T) ? x[0,u,0] : x[u-T+1, T-1, 0]
    #pragma unroll 4
    for (int idx = tid; idx < SLICE; idx += K2_BT) {
        int u = slice_base + idx;
        float v = 1.0f;
        if (u >= 0 && u < NTS)
            v = (u < TDIM) ? x[u] : x[(u - (TDIM - 1)) * TDIM + (TDIM - 1)];
        sm_ts[idx] = v;
    }
    __syncthreads();

    const float a  = *alpha_p;
    const float g  = *gamma_p;
    const float ka = 1.0f - a;
    const float kg = 1.0f - g;

    const int chunk = blockIdx.x * K2_BT + tid;
    const int t0    = chunk * CH_S;
    const int u0    = t0 - W_UP;

    float l = *level_p;
    float q[MQ];
    float iq[MQ];
    // slot used at step u is (u - u0) mod 24 == (u - t0) mod 24 (W_UP%24==0);
    // q[j] = inits[(j + t0) % 24] puts inits[0] at u = 0.
    {
        int ph = t0 % MQ;
#pragma unroll
        for (int j = 0; j < MQ; j++) {
            int idx = j + ph; if (idx >= MQ) idx -= MQ;
            q[j] = inits[idx];
        }
#pragma unroll
        for (int j = 0; j < MQ; j++) iq[j] = frcp(q[j]);
    }

    const int base = tid * CH_S;   // sm_ts index of this thread's u0

    // ---- clamped prefix (threads with t0 < W_UP; blocks 0..2 only) ----
    // macros fully below t=0 are skipped; at most one macro is step-guarded.
    int kk = 0;
    if (u0 < 0) {
        int m   = (-u0) / MQ;      // fully-skipped macros
        int rem = (-u0) % MQ;      // first 'rem' steps of macro m are skipped
        kk = m;
        if (rem > 0) {
            int off = base + kk * MQ;
#pragma unroll
            for (int j = 0; j < MQ; j++) {
                if (j >= rem) {
                    float y  = sm_ts[off + j];
                    float r  = y * iq[j];
                    l        = fmaf(ka, l, a * r);
                    float il = frcp(l);
                    float sn = fmaf(kg, q[j], (g * y) * il);
                    q[j]  = sn;
                    iq[j] = frcp(sn);
                }
            }
            kk++;
        }
    }

    // ---- clean warm loop: phase-decomposed 24-step macros ----
    for (; kk < WMACRO; kk++) {
        const int off = base + kk * MQ;
        float y[MQ];
        float r[MQ];
        float il[MQ];
        // phase 1: batched loads (one LDS latency per macro)
#pragma unroll
        for (int j = 0; j < MQ; j++) y[j] = sm_ts[off + j];
        // phase 2: independent ratios (iq from previous macro)
#pragma unroll
        for (int j = 0; j < MQ; j++) r[j] = y[j] * iq[j];
        // phase 3: the true serial chain -- 24 dependent FFMAs (4 cyc each)
#pragma unroll
        for (int j = 0; j < MQ; j++) { l = fmaf(ka, l, a * r[j]); r[j] = l; }
        // phase 4a: 24 independent MUFUs -- pipeline at rt 8
#pragma unroll
        for (int j = 0; j < MQ; j++) il[j] = frcp(r[j]);
        // phase 4b: 24 independent FMUL+FFMA on the fma pipe
#pragma unroll
        for (int j = 0; j < MQ; j++) q[j] = fmaf(kg, q[j], (g * y[j]) * il[j]);
        // phase 4c: 24 independent MUFUs
#pragma unroll
        for (int j = 0; j < MQ; j++) iq[j] = frcp(q[j]);
    }

    g_lstart[chunk] = l;                  // level entering t0 (pre-update)

    // ---- output phase: 19 steps; slots wrap from 0 (W_UP % 24 == 0) ----
    {
        const int off = base + WMACRO * MQ;
        const int oo  = tid * CH_S;
        float y[CH_S];
        float r[CH_S];
        float il[CH_S];
#pragma unroll
        for (int c = 0; c < CH_S; c++) y[c] = sm_ts[off + c];
#pragma unroll
        for (int c = 0; c < CH_S; c++) r[c] = y[c] * iq[c];
#pragma unroll
        for (int c = 0; c < CH_S; c++) { l = fmaf(ka, l, a * r[c]); sm_l[oo + c] = l; r[c] = l; }
#pragma unroll
        for (int c = 0; c < CH_S; c++) il[c] = frcp(r[c]);
#pragma unroll
        for (int c = 0; c < CH_S; c++) sm_s[oo + c] = fmaf(kg, q[c], (g * y[c]) * il[c]);
#pragma unroll
        for (int c = 0; c < CH_S; c++) sm_xn[oo + c] = (y[c] * iq[c]) * il[c];
    }
    g_lend[chunk] = l;                    // level entering t0 + 19

    __syncthreads();
    int span = NTS - blk_t0; if (span > BSPAN) span = BSPAN;
    for (int idx = tid; idx < span; idx += K2_BT) {
        g_xn[blk_t0 + idx] = sm_xn[idx];
        g_l [blk_t0 + idx] = sm_l [idx];
        g_s [blk_t0 + idx] = sm_s [idx];
    }
}

// ============ K2: prefix product + in-place correction (R1 verbatim) ======
__global__ __launch_bounds__(NCHUNK) void k_correct() {
    __shared__ float c[NCHUNK];
    int k = threadIdx.x;
    float ratio = 1.0f;
    if (k > 0 && k * CH_S < NTS) ratio = g_lstart[k] / g_lend[k - 1];
    c[k] = ratio;
    __syncthreads();
    for (int o = 1; o < NCHUNK; o <<= 1) {
        float v = (k >= o) ? c[k - o] : 1.0f;
        __syncthreads();
        c[k] *= v;
        __syncthreads();
    }
    for (int t = k; t < NTS; t += NCHUNK) {
        float cc = c[t / CH_S];
        g_l[t] = g_l[t] / cc;
        g_s[t] = g_s[t] * cc;
    }
}

// ============ K3: fused x_out + denorm ============
__global__ void k_out(float* __restrict__ out) {
    int bx = blockIdx.x;
    if (bx < XB) {
        int i4   = bx * blockDim.x + threadIdx.x;
        int i    = i4 << 2;
        int b    = i >> 11;
        int t    = i & (TDIM - 1);
        int base = b + t;
        int qq   = base >> 2;
        int sh   = base & 3;
        const float4* xn4 = reinterpret_cast<const float4*>(g_xn);
        float4 f0 = xn4[qq];
        float4 v;
        if (sh == 0) {
            v = f0;
        } else {
            float4 f1 = xn4[qq + 1];
            if (sh == 1)      v = make_float4(f0.y, f0.z, f0.w, f1.x);
            else if (sh == 2) v = make_float4(f0.z, f0.w, f1.x, f1.y);
            else              v = make_float4(f0.w, f1.x, f1.y, f1.z);
        }
        reinterpret_cast<float4*>(out)[i4] = v;
    } else {
        int i = (bx - XB) * blockDim.x + threadIdx.x;
        if (i < DEN_N) {
            int b = i / 48;
            int r = i - b * 48;
            int h = r >> 1;
            out[XOUT_N + i] = (r & 1) ? g_s[(TDIM - MQ) + b + h]
                                      : g_l[(TDIM - 1) + b];
        }
    }
}

extern "C" void kernel_launch(void* const* d_in, const int* in_sizes, int n_in,
                              void* d_out, int out_size) {
    const float* x     = (const float*)d_in[0];
    const float* alpha = (const float*)d_in[1];
    const float* gamma = (const float*)d_in[2];
    const float* inits = (const float*)d_in[3];
    const float* level = (const float*)d_in[4];
    float* out = (float*)d_out;

    k_scan<<<K2_NB, K2_BT>>>(x, alpha, gamma, inits, level);
    k_correct<<<1, NCHUNK>>>();
    int nb = (out_size >= XOUT_N + DEN_N) ? (XB + DB) : XB;
    k_out<<<nb, 256>>>(out);
}

// round 7
// speedup vs baseline: 2.6491x; 1.5889x over previous
#include <cuda_runtime.h>

// ---------------- problem constants ----------------
#define TDIM   2048
#define BDIM   16384
#define NTS    18431            // TDIM + BDIM - 1
#define MQ     24               // seasonality period == HORIZON
#define XOUT_N (BDIM * TDIM)    // 33554432
#define DEN_N  (BDIM * 48)      // 786432

// ---------------- chunk-parallel scan config ----------------
#define W_UP   1440             // warm-up steps (60 seasonal cycles)
#define WMACRO (W_UP / MQ)      // 60
#define CH_S   19               // output steps per chunk
#define WPB    4                // warps (=chunks) per block
#define K3_BT  (WPB * 32)       // 128 threads
#define K3_NB  243              // ceil(971/4) -> 972 chunk slots
#define NCHUNK 1024             // logical chunk-index space
#define BSPAN  (WPB * CH_S)     // 76 output steps per block
#define SLICE  (W_UP + BSPAN)   // 1516 ts floats actually used
#define SLICEP (SLICE + 32)     // padded: lanes 24..31 overread harmlessly

#define XB     (XOUT_N / 4 / 256)        // 32768 xout blocks
#define DB     ((DEN_N + 255) / 256)     // 3072 denorm blocks

// ---------------- device scratch (no allocs allowed) ----------------
__device__ __align__(16) float g_xn[18448];   // padded for float4 reads
__device__ float g_l [NTS];
__device__ float g_s [NTS];
__device__ float g_lstart[NCHUNK];
__device__ float g_lend  [NCHUNK];

__device__ __forceinline__ float frcp(float x) {
    float r;
    asm("rcp.approx.ftz.f32 %0, %1;" : "=f"(r) : "f"(x));
    return r;
}

// ============ K1: lane-per-slot warp-parallel ES scan ============
// One warp = one 19-step chunk warm-started 1440 steps back. Lane j owns
// seasonal slot j (period 24). Per 24-step macro: lane-parallel ratio,
// Kogge-Stone affine scan for the level chain (l_u = ka*l + a*r_u), then
// ONE rcp(l)+fma+rcp(sn) per lane. 2 MUFU warp-instrs per macro (was 48).
__global__ __launch_bounds__(K3_BT) void k_scan(
    const float* __restrict__ x,
    const float* __restrict__ alpha_p, const float* __restrict__ gamma_p,
    const float* __restrict__ inits,   const float* __restrict__ level_p)
{
    __shared__ float sm_ts[SLICEP];
    __shared__ float sm_xn[BSPAN];
    __shared__ float sm_l [BSPAN];
    __shared__ float sm_s [BSPAN];

    const int tid        = threadIdx.x;
    const int wid        = tid >> 5;
    const int lane       = tid & 31;
    const int blk_t0     = blockIdx.x * BSPAN;
    const int slice_base = blk_t0 - W_UP;

    // stage ts slice: ts[u] = (u < T) ? x[0,u,0] : x[u-T+1, T-1, 0]
    for (int idx = tid; idx < SLICEP; idx += K3_BT) {
        int u = slice_base + idx;
        float v = 1.0f;
        if (u >= 0 && u < NTS)
            v = (u < TDIM) ? x[u] : x[(u - (TDIM - 1)) * TDIM + (TDIM - 1)];
        sm_ts[idx] = v;
    }
    __syncthreads();

    const float a  = *alpha_p;
    const float g  = *gamma_p;
    const float ka = 1.0f - a;
    const float kg = 1.0f - g;
    const float ka2 = ka * ka, ka4 = ka2 * ka2, ka8 = ka4 * ka4, ka16 = ka8 * ka8;

    const int chunk = blockIdx.x * WPB + wid;
    const int t0    = chunk * CH_S;
    const int u0    = t0 - W_UP;
    const int base  = wid * CH_S;      // sm_ts index of this warp's u0

    // per-lane constant ka^(lane+1)
    float kaPow = ka;
    for (int i = 0; i < lane; i++) kaPow *= ka;

    // lane j owns slot j: q = inits[(j + t0) % 24]
    float q, iq;
    {
        int idx = (lane + t0) % MQ;
        q  = inits[idx];
        iq = frcp(q);
    }
    float l = *level_p;

    int kk = 0;
    // ---- clamped prefix (chunks with t0 < W_UP): skip whole macros; one
    // partial macro where lanes j < rem use identity affines & skip updates.
    if (u0 < 0) {
        int m   = (-u0) / MQ;
        int rem = (-u0) % MQ;
        kk = m;
        if (rem > 0) {
            int off = base + kk * MQ;
            float y = sm_ts[off + lane];
            float r = y * iq;
            bool act = (lane >= rem);
            float Av = act ? ka      : 1.0f;
            float Bv = act ? a * r   : 0.0f;
#pragma unroll
            for (int s = 1; s < MQ; s <<= 1) {
                float Bp = __shfl_up_sync(0xffffffffu, Bv, s);
                float Ap = __shfl_up_sync(0xffffffffu, Av, s);
                if (lane >= s) { Bv = fmaf(Av, Bp, Bv); Av *= Ap; }
            }
            float ll = fmaf(Av, l, Bv);
            if (act) {
                float il = frcp(ll);
                float sn = fmaf(kg, q, (g * y) * il);
                q  = sn;
                iq = frcp(sn);
            }
            l = __shfl_sync(0xffffffffu, ll, MQ - 1);
            kk++;
        }
    }

    // ---- clean warm loop ----
    for (; kk < WMACRO; kk++) {
        int off = base + kk * MQ;
        float y = sm_ts[off + lane];
        float r = y * iq;
        float B = a * r;
        float Bp;
        Bp = __shfl_up_sync(0xffffffffu, B, 1);  if (lane >= 1)  B = fmaf(ka,   Bp, B);
        Bp = __shfl_up_sync(0xffffffffu, B, 2);  if (lane >= 2)  B = fmaf(ka2,  Bp, B);
        Bp = __shfl_up_sync(0xffffffffu, B, 4);  if (lane >= 4)  B = fmaf(ka4,  Bp, B);
        Bp = __shfl_up_sync(0xffffffffu, B, 8);  if (lane >= 8)  B = fmaf(ka8,  Bp, B);
        Bp = __shfl_up_sync(0xffffffffu, B, 16); if (lane >= 16) B = fmaf(ka16, Bp, B);
        float ll = fmaf(kaPow, l, B);
        float il = frcp(ll);
        float sn = fmaf(kg, q, (g * y) * il);
        q  = sn;
        iq = frcp(sn);
        l  = __shfl_sync(0xffffffffu, ll, MQ - 1);
    }

    if (lane == 0) g_lstart[chunk] = l;    // level entering t0

    // ---- output phase: 19 steps (lanes 0..18 produce results) ----
    {
        int off = base + WMACRO * MQ;
        float y = sm_ts[off + lane];
        float r = y * iq;
        float B = a * r;
        float Bp;
        Bp = __shfl_up_sync(0xffffffffu, B, 1);  if (lane >= 1)  B = fmaf(ka,   Bp, B);
        Bp = __shfl_up_sync(0xffffffffu, B, 2);  if (lane >= 2)  B = fmaf(ka2,  Bp, B);
        Bp = __shfl_up_sync(0xffffffffu, B, 4);  if (lane >= 4)  B = fmaf(ka4,  Bp, B);
        Bp = __shfl_up_sync(0xffffffffu, B, 8);  if (lane >= 8)  B = fmaf(ka8,  Bp, B);
        Bp = __shfl_up_sync(0xffffffffu, B, 16); if (lane >= 16) B = fmaf(ka16, Bp, B);
        float ll = fmaf(kaPow, l, B);
        float il = frcp(ll);
        float sn = fmaf(kg, q, (g * y) * il);
        if (lane < CH_S) {
            int oo = base + lane;
            sm_xn[oo] = r * il;
            sm_l [oo] = ll;
            sm_s [oo] = sn;
        }
        float le = __shfl_sync(0xffffffffu, ll, CH_S - 1);
        if (lane == 0) g_lend[chunk] = le;   // level entering t0 + 19
    }

    __syncthreads();
    int span = NTS - blk_t0; if (span > BSPAN) span = BSPAN;
    for (int idx = tid; idx < span; idx += K3_BT) {
        g_xn[blk_t0 + idx] = sm_xn[idx];
        g_l [blk_t0 + idx] = sm_l [idx];
        g_s [blk_t0 + idx] = sm_s [idx];
    }
}

// ============ K2: prefix product + in-place correction ============
// ratio_k = lstart_k / lend_{k-1} = c_k / c_{k-1}; c_0 = 1 (exact start).
__global__ __launch_bounds__(NCHUNK) void k_correct() {
    __shared__ float c[NCHUNK];
    int k = threadIdx.x;
    float ratio = 1.0f;
    if (k > 0 && k * CH_S < NTS) ratio = g_lstart[k] / g_lend[k - 1];
    c[k] = ratio;
    __syncthreads();
    for (int o = 1; o < NCHUNK; o <<= 1) {
        float v = (k >= o) ? c[k - o] : 1.0f;
        __syncthreads();
        c[k] *= v;
        __syncthreads();
    }
    for (int t = k; t < NTS; t += NCHUNK) {
        float cc = c[t / CH_S];
        g_l[t] = g_l[t] / cc;
        g_s[t] = g_s[t] * cc;
    }
}

// ============ K3: fused x_out + denorm ============
__global__ void k_out(float* __restrict__ out) {
    int bx = blockIdx.x;
    if (bx < XB) {
        int i4   = bx * blockDim.x + threadIdx.x;
        int i    = i4 << 2;
        int b    = i >> 11;
        int t    = i & (TDIM - 1);
        int base = b + t;
        int qq   = base >> 2;
        int sh   = base & 3;
        const float4* xn4 = reinterpret_cast<const float4*>(g_xn);
        float4 f0 = xn4[qq];
        float4 v;
        if (sh == 0) {
            v = f0;
        } else {
            float4 f1 = xn4[qq + 1];
            if (sh == 1)      v = make_float4(f0.y, f0.z, f0.w, f1.x);
            else if (sh == 2) v = make_float4(f0.z, f0.w, f1.x, f1.y);
            else              v = make_float4(f0.w, f1.x, f1.y, f1.z);
        }
        reinterpret_cast<float4*>(out)[i4] = v;
    } else {
        int i = (bx - XB) * blockDim.x + threadIdx.x;
        if (i < DEN_N) {
            int b = i / 48;
            int r = i - b * 48;
            int h = r >> 1;
            out[XOUT_N + i] = (r & 1) ? g_s[(TDIM - MQ) + b + h]
                                      : g_l[(TDIM - 1) + b];
        }
    }
}

extern "C" void kernel_launch(void* const* d_in, const int* in_sizes, int n_in,
                              void* d_out, int out_size) {
    const float* x     = (const float*)d_in[0];
    const float* alpha = (const float*)d_in[1];
    const float* gamma = (const float*)d_in[2];
    const float* inits = (const float*)d_in[3];
    const float* level = (const float*)d_in[4];
    float* out = (float*)d_out;

    k_scan<<<K3_NB, K3_BT>>>(x, alpha, gamma, inits, level);
    k_correct<<<1, NCHUNK>>>();
    int nb = (out_size >= XOUT_N + DEN_N) ? (XB + DB) : XB;
    k_out<<<nb, 256>>>(out);
}